// round 10
// baseline (speedup 1.0000x reference)
#include <cuda_runtime.h>
#include <math.h>

#define NCAT   1024
#define INDIM  1024
#define HDIM   2048
#define GDIM   (4 * HDIM)      // 8192
#define OUTDIM 32000
#define WOUT_K (NCAT + HDIM)   // 3072

#define A_BLOCKS 512     // gates0
#define B_BLOCKS 512     // gates1 base (w_hh_l1 @ h0)
#define C_BLOCKS 2000    // logits cat part
#define D_BLOCKS 512     // gates1 ih part (w_ih_l1 @ h1)
#define E_BLOCKS 2000    // logits h part (w_out[:,1024:] @ h2)
#define TOTAL_BLOCKS (A_BLOCKS + B_BLOCKS + C_BLOCKS + D_BLOCKS + E_BLOCKS)  // 5536

// Scratch (no allocations allowed)
__device__ float g_gates0[GDIM];
__device__ float g_gates1[GDIM];    // base: w_hh_l1@h0 + biases
__device__ float g_gates1b[GDIM];   // ih part: w_ih_l1@h1
__device__ float g_h1[HDIM];
__device__ float g_h2[HDIM];
__device__ float g_logits[OUTDIM];    // cat part + bias
__device__ float g_logits_h[OUTDIM];  // h2 part
__device__ unsigned int g_cntA = 0, g_cntB = 0, g_cntD = 0, g_cntE = 0;
__device__ unsigned int g_flag1 = 0, g_flag2 = 0;

__device__ __forceinline__ float f4dot(float4 a, float4 b) {
    return a.x * b.x + a.y * b.y + a.z * b.z + a.w * b.w;
}
__device__ __forceinline__ float warp_reduce(float acc) {
#pragma unroll
    for (int off = 16; off; off >>= 1)
        acc += __shfl_down_sync(0xffffffffu, acc, off);
    return acc;
}
__device__ __forceinline__ float fast_sigmoid(float x) {
    return 1.0f / (1.0f + __expf(-x));
}
__device__ __forceinline__ float fast_tanh(float x) {
    return 1.0f - 2.0f / (__expf(2.0f * x) + 1.0f);
}
__device__ __forceinline__ void spin_on_flag(volatile unsigned int* f) {
    if (threadIdx.x == 0) {
        while (*f == 0u) __nanosleep(128);
    }
    __syncthreads();
    __threadfence();
}

// ---------------------------------------------------------------------------
// Mega-kernel: the whole LSTM chain except log_softmax.
__global__ void __launch_bounds__(256) mega_kernel(
    const float* __restrict__ cat, const float* __restrict__ inp,
    const float* __restrict__ hidden, const float* __restrict__ cell,
    const float* __restrict__ w_ih_l0, const float* __restrict__ w_hh_l0,
    const float* __restrict__ b_ih_l0, const float* __restrict__ b_hh_l0,
    const float* __restrict__ w_ih_l1, const float* __restrict__ w_hh_l1,
    const float* __restrict__ b_ih_l1, const float* __restrict__ b_hh_l1,
    const float* __restrict__ w_out, const float* __restrict__ b_out,
    float* __restrict__ out_h1, float* __restrict__ out_c1,
    float* __restrict__ out_h2, float* __restrict__ out_c2)
{
    int b = blockIdx.x;
    int lane = threadIdx.x & 31;
    int wlocal = threadIdx.x >> 5;  // 0..7

    if (b < A_BLOCKS) {
        // ---- A: gates0 rows, 2 rows/warp ----
        int r0 = (b * 8 + wlocal) * 2, r1 = r0 + 1;
        const float4* a0 = (const float4*)(w_ih_l0 + (size_t)r0 * 2048);
        const float4* a1 = (const float4*)(w_ih_l0 + (size_t)r1 * 2048);
        const float4* h0 = (const float4*)(w_hh_l0 + (size_t)r0 * 2048);
        const float4* h1 = (const float4*)(w_hh_l0 + (size_t)r1 * 2048);
        const float4* vc = (const float4*)cat;
        const float4* vi = (const float4*)inp;
        const float4* vh = (const float4*)hidden;
        float acc0 = 0.f, acc1 = 0.f;
#pragma unroll
        for (int i = 0; i < 8; i++) {
            float4 x = vc[lane + 32 * i];
            acc0 += f4dot(__ldcs(&a0[lane + 32 * i]), x);
            acc1 += f4dot(__ldcs(&a1[lane + 32 * i]), x);
        }
#pragma unroll
        for (int i = 0; i < 8; i++) {
            float4 x = vi[lane + 32 * i];
            acc0 += f4dot(__ldcs(&a0[256 + lane + 32 * i]), x);
            acc1 += f4dot(__ldcs(&a1[256 + lane + 32 * i]), x);
        }
#pragma unroll
        for (int i = 0; i < 16; i++) {
            float4 x = vh[lane + 32 * i];
            acc0 += f4dot(__ldcs(&h0[lane + 32 * i]), x);
            acc1 += f4dot(__ldcs(&h1[lane + 32 * i]), x);
        }
        acc0 = warp_reduce(acc0);
        acc1 = warp_reduce(acc1);
        if (lane == 0) {
            g_gates0[r0] = acc0 + b_ih_l0[r0] + b_hh_l0[r0];
            g_gates0[r1] = acc1 + b_ih_l0[r1] + b_hh_l0[r1];
        }
        __threadfence();
        __shared__ bool is_last;
        __syncthreads();
        if (threadIdx.x == 0) {
            unsigned int v = atomicAdd(&g_cntA, 1u);
            is_last = (v == A_BLOCKS - 1u);
            if (is_last) g_cntA = 0u;
        }
        __syncthreads();
        if (is_last) {
            __threadfence();
            for (int j = threadIdx.x; j < HDIM; j += 256) {
                float ig = fast_sigmoid(g_gates0[j]);
                float fg = fast_sigmoid(g_gates0[HDIM + j]);
                float gg = fast_tanh(g_gates0[2 * HDIM + j]);
                float og = fast_sigmoid(g_gates0[3 * HDIM + j]);
                float c_new = fg * cell[j] + ig * gg;
                float h_new = og * fast_tanh(c_new);
                g_h1[j] = h_new;
                out_h1[j] = h_new;
                out_c1[j] = c_new;
            }
            __threadfence();
            __syncthreads();
            if (threadIdx.x == 0) atomicExch(&g_flag1, 1u);
        }
    } else if (b < A_BLOCKS + B_BLOCKS) {
        // ---- B: gates1 base = w_hh_l1 @ h0_1 + biases ----
        int bb = b - A_BLOCKS;
        int r0 = (bb * 8 + wlocal) * 2, r1 = r0 + 1;
        const float4* w0 = (const float4*)(w_hh_l1 + (size_t)r0 * 2048);
        const float4* w1 = (const float4*)(w_hh_l1 + (size_t)r1 * 2048);
        const float4* vh = (const float4*)(hidden + HDIM);
        float acc0 = 0.f, acc1 = 0.f;
#pragma unroll
        for (int i = 0; i < 16; i++) {
            float4 x = vh[lane + 32 * i];
            acc0 += f4dot(__ldcs(&w0[lane + 32 * i]), x);
            acc1 += f4dot(__ldcs(&w1[lane + 32 * i]), x);
        }
        acc0 = warp_reduce(acc0);
        acc1 = warp_reduce(acc1);
        if (lane == 0) {
            g_gates1[r0] = acc0 + b_ih_l1[r0] + b_hh_l1[r0];
            g_gates1[r1] = acc1 + b_ih_l1[r1] + b_hh_l1[r1];
        }
        __threadfence();
        __syncthreads();
        if (threadIdx.x == 0) atomicAdd(&g_cntB, 1u);
    } else if (b < A_BLOCKS + B_BLOCKS + C_BLOCKS) {
        // ---- C: logits cat part + bias ----
        int cb = b - (A_BLOCKS + B_BLOCKS);
        int r0 = (cb * 8 + wlocal) * 2, r1 = r0 + 1;
        const float4* w0 = (const float4*)(w_out + (size_t)r0 * WOUT_K);
        const float4* w1 = (const float4*)(w_out + (size_t)r1 * WOUT_K);
        const float4* vc = (const float4*)cat;
        float acc0 = 0.f, acc1 = 0.f;
#pragma unroll
        for (int i = 0; i < 8; i++) {
            float4 x = vc[lane + 32 * i];
            acc0 += f4dot(__ldcs(&w0[lane + 32 * i]), x);
            acc1 += f4dot(__ldcs(&w1[lane + 32 * i]), x);
        }
        acc0 = warp_reduce(acc0);
        acc1 = warp_reduce(acc1);
        if (lane == 0) {
            g_logits[r0] = acc0 + b_out[r0];
            g_logits[r1] = acc1 + b_out[r1];
        }
    } else if (b < A_BLOCKS + B_BLOCKS + C_BLOCKS + D_BLOCKS) {
        // ---- D: gates1 ih part = w_ih_l1 @ h1 (needs flag1/h1) ----
        spin_on_flag(&g_flag1);
        int db = b - (A_BLOCKS + B_BLOCKS + C_BLOCKS);
        int r0 = (db * 8 + wlocal) * 2, r1 = r0 + 1;
        const float4* w0 = (const float4*)(w_ih_l1 + (size_t)r0 * 2048);
        const float4* w1 = (const float4*)(w_ih_l1 + (size_t)r1 * 2048);
        const float4* vh = (const float4*)g_h1;
        float acc0 = 0.f, acc1 = 0.f;
#pragma unroll
        for (int i = 0; i < 16; i++) {
            float4 x = vh[lane + 32 * i];
            acc0 += f4dot(__ldcs(&w0[lane + 32 * i]), x);
            acc1 += f4dot(__ldcs(&w1[lane + 32 * i]), x);
        }
        acc0 = warp_reduce(acc0);
        acc1 = warp_reduce(acc1);
        if (lane == 0) {
            g_gates1b[r0] = acc0;
            g_gates1b[r1] = acc1;
        }
        __threadfence();
        __shared__ bool is_last;
        __syncthreads();
        if (threadIdx.x == 0) {
            unsigned int v = atomicAdd(&g_cntD, 1u);
            is_last = (v == D_BLOCKS - 1u);
            if (is_last) g_cntD = 0u;
        }
        __syncthreads();
        if (is_last) {
            if (threadIdx.x == 0) {
                g_flag1 = 0u;  // all D passed the spin; reset for next replay
                while (atomicAdd(&g_cntB, 0u) < B_BLOCKS) __nanosleep(64);
                g_cntB = 0u;
            }
            __syncthreads();
            __threadfence();
            for (int j = threadIdx.x; j < HDIM; j += 256) {
                float s0 = g_gates1[j]          + g_gates1b[j];
                float s1 = g_gates1[HDIM + j]   + g_gates1b[HDIM + j];
                float s2 = g_gates1[2*HDIM + j] + g_gates1b[2*HDIM + j];
                float s3 = g_gates1[3*HDIM + j] + g_gates1b[3*HDIM + j];
                float ig = fast_sigmoid(s0);
                float fg = fast_sigmoid(s1);
                float gg = fast_tanh(s2);
                float og = fast_sigmoid(s3);
                float c_new = fg * cell[HDIM + j] + ig * gg;
                float h_new = og * fast_tanh(c_new);
                g_h2[j] = h_new;
                out_h2[j] = h_new;
                out_c2[j] = c_new;
            }
            __threadfence();
            __syncthreads();
            if (threadIdx.x == 0) atomicExch(&g_flag2, 1u);
        }
    } else {
        // ---- E: logits h part = w_out[:,1024:] @ h2 (needs flag2/h2) ----
        spin_on_flag(&g_flag2);
        int eb = b - (A_BLOCKS + B_BLOCKS + C_BLOCKS + D_BLOCKS);
        int r0 = (eb * 8 + wlocal) * 2, r1 = r0 + 1;
        const float4* w0 = (const float4*)(w_out + (size_t)r0 * WOUT_K + NCAT);
        const float4* w1 = (const float4*)(w_out + (size_t)r1 * WOUT_K + NCAT);
        const float4* vh = (const float4*)g_h2;
        float acc0 = 0.f, acc1 = 0.f;
#pragma unroll
        for (int i = 0; i < 16; i++) {
            float4 x = vh[lane + 32 * i];
            acc0 += f4dot(__ldcs(&w0[lane + 32 * i]), x);
            acc1 += f4dot(__ldcs(&w1[lane + 32 * i]), x);
        }
        acc0 = warp_reduce(acc0);
        acc1 = warp_reduce(acc1);
        if (lane == 0) {
            g_logits_h[r0] = acc0;
            g_logits_h[r1] = acc1;
        }
        __syncthreads();
        if (threadIdx.x == 0) {
            unsigned int v = atomicAdd(&g_cntE, 1u);
            if (v == E_BLOCKS - 1u) { g_cntE = 0u; g_flag2 = 0u; }
        }
    }
}

// ---------------------------------------------------------------------------
// log_softmax over g_logits + g_logits_h; one 1024-thread block.
__global__ void log_softmax_kernel(float* __restrict__ out) {
    __shared__ float red[32];
    int tid = threadIdx.x;
    int lane = tid & 31;
    int wid = tid >> 5;

    float m = -INFINITY;
    for (int i = tid; i < OUTDIM; i += 1024)
        m = fmaxf(m, g_logits[i] + g_logits_h[i]);
#pragma unroll
    for (int off = 16; off; off >>= 1)
        m = fmaxf(m, __shfl_xor_sync(0xffffffffu, m, off));
    if (lane == 0) red[wid] = m;
    __syncthreads();
    if (wid == 0) {
        float v = red[lane];
#pragma unroll
        for (int off = 16; off; off >>= 1)
            v = fmaxf(v, __shfl_xor_sync(0xffffffffu, v, off));
        if (lane == 0) red[0] = v;
    }
    __syncthreads();
    m = red[0];
    __syncthreads();

    float s = 0.f;
    for (int i = tid; i < OUTDIM; i += 1024)
        s += __expf(g_logits[i] + g_logits_h[i] - m);
#pragma unroll
    for (int off = 16; off; off >>= 1)
        s += __shfl_xor_sync(0xffffffffu, s, off);
    if (lane == 0) red[wid] = s;
    __syncthreads();
    if (wid == 0) {
        float v = red[lane];
#pragma unroll
        for (int off = 16; off; off >>= 1)
            v += __shfl_xor_sync(0xffffffffu, v, off);
        if (lane == 0) red[0] = v;
    }
    __syncthreads();
    float lse = m + __logf(red[0]);

    for (int i = tid; i < OUTDIM; i += 1024)
        out[i] = g_logits[i] + g_logits_h[i] - lse;
}

// ---------------------------------------------------------------------------
extern "C" void kernel_launch(void* const* d_in, const int* in_sizes, int n_in,
                              void* d_out, int out_size) {
    const float* category = (const float*)d_in[0];
    const float* input    = (const float*)d_in[1];
    const float* hidden   = (const float*)d_in[2];
    const float* cell     = (const float*)d_in[3];
    const float* w_ih_l0  = (const float*)d_in[4];
    const float* w_hh_l0  = (const float*)d_in[5];
    const float* b_ih_l0  = (const float*)d_in[6];
    const float* b_hh_l0  = (const float*)d_in[7];
    const float* w_ih_l1  = (const float*)d_in[8];
    const float* w_hh_l1  = (const float*)d_in[9];
    const float* b_ih_l1  = (const float*)d_in[10];
    const float* b_hh_l1  = (const float*)d_in[11];
    const float* w_out    = (const float*)d_in[12];
    const float* b_out    = (const float*)d_in[13];

    float* out = (float*)d_out;
    float* out_logp = out;
    float* out_h1 = out + OUTDIM;
    float* out_h2 = out + OUTDIM + HDIM;
    float* out_c1 = out + OUTDIM + 2 * HDIM;
    float* out_c2 = out + OUTDIM + 3 * HDIM;

    mega_kernel<<<TOTAL_BLOCKS, 256>>>(
        category, input, hidden, cell,
        w_ih_l0, w_hh_l0, b_ih_l0, b_hh_l0,
        w_ih_l1, w_hh_l1, b_ih_l1, b_hh_l1,
        w_out, b_out,
        out_h1, out_c1, out_h2, out_c2);

    log_softmax_kernel<<<1, 1024>>>(out_logp);
}

// round 11
// speedup vs baseline: 1.1218x; 1.1218x over previous
#include <cuda_runtime.h>
#include <math.h>

#define NCAT   1024
#define INDIM  1024
#define HDIM   2048
#define GDIM   (4 * HDIM)      // 8192
#define OUTDIM 32000
#define WOUT_K (NCAT + HDIM)   // 3072

#define SMX_CHUNKS 64
#define SMX_CHUNK  (OUTDIM / SMX_CHUNKS)  // 500

// Scratch (no allocations allowed)
__device__ float g_gates0[GDIM];
__device__ float g_gates1[GDIM];
__device__ float g_h1[HDIM];
__device__ float g_h2[HDIM];
__device__ float g_logits[OUTDIM];
__device__ float g_pmax[SMX_CHUNKS];
__device__ float g_psum[SMX_CHUNKS];
__device__ unsigned int g_cnt0 = 0;

__device__ __forceinline__ float f4dot(float4 a, float4 b) {
    return a.x * b.x + a.y * b.y + a.z * b.z + a.w * b.w;
}
__device__ __forceinline__ float warp_reduce(float acc) {
#pragma unroll
    for (int off = 16; off; off >>= 1)
        acc += __shfl_down_sync(0xffffffffu, acc, off);
    return acc;
}
__device__ __forceinline__ float fast_sigmoid(float x) {
    return 1.0f / (1.0f + __expf(-x));
}
__device__ __forceinline__ float fast_tanh(float x) {
    return 1.0f - 2.0f / (__expf(2.0f * x) + 1.0f);
}

// ---------------------------------------------------------------------------
// K1: all input-only matvecs, 2 rows per warp.
//   blocks [0, 512):     gates0 rows; last one also runs cell0
//   blocks [512, 1024):  gates1 partial rows
//   blocks [1024, 3024): logits-cat rows
__global__ void __launch_bounds__(256, 4) k1_input_matvecs(
    const float* __restrict__ cat, const float* __restrict__ inp,
    const float* __restrict__ hidden, const float* __restrict__ cell,
    const float* __restrict__ w_ih_l0, const float* __restrict__ w_hh_l0,
    const float* __restrict__ b_ih_l0, const float* __restrict__ b_hh_l0,
    const float* __restrict__ w_hh_l1,
    const float* __restrict__ b_ih_l1, const float* __restrict__ b_hh_l1,
    const float* __restrict__ w_out, const float* __restrict__ b_out,
    float* __restrict__ out_h1, float* __restrict__ out_c1)
{
    int W = (blockIdx.x * blockDim.x + threadIdx.x) >> 5;
    int lane = threadIdx.x & 31;

    if (W < GDIM / 2) {
        int r0 = 2 * W, r1 = r0 + 1;
        const float4* a0 = (const float4*)(w_ih_l0 + (size_t)r0 * 2048);
        const float4* a1 = (const float4*)(w_ih_l0 + (size_t)r1 * 2048);
        const float4* h0 = (const float4*)(w_hh_l0 + (size_t)r0 * 2048);
        const float4* h1 = (const float4*)(w_hh_l0 + (size_t)r1 * 2048);
        const float4* vc = (const float4*)cat;
        const float4* vi = (const float4*)inp;
        const float4* vh = (const float4*)hidden;
        float acc0 = 0.f, acc1 = 0.f;
#pragma unroll
        for (int i = 0; i < 8; i++) {
            float4 x = vc[lane + 32 * i];
            acc0 += f4dot(__ldcs(&a0[lane + 32 * i]), x);
            acc1 += f4dot(__ldcs(&a1[lane + 32 * i]), x);
        }
#pragma unroll
        for (int i = 0; i < 8; i++) {
            float4 x = vi[lane + 32 * i];
            acc0 += f4dot(__ldcs(&a0[256 + lane + 32 * i]), x);
            acc1 += f4dot(__ldcs(&a1[256 + lane + 32 * i]), x);
        }
#pragma unroll
        for (int i = 0; i < 16; i++) {
            float4 x = vh[lane + 32 * i];
            acc0 += f4dot(__ldcs(&h0[lane + 32 * i]), x);
            acc1 += f4dot(__ldcs(&h1[lane + 32 * i]), x);
        }
        acc0 = warp_reduce(acc0);
        acc1 = warp_reduce(acc1);
        if (lane == 0) {
            g_gates0[r0] = acc0 + b_ih_l0[r0] + b_hh_l0[r0];
            g_gates0[r1] = acc1 + b_ih_l0[r1] + b_hh_l0[r1];
        }

        // cell0 in the last gates0 block — overlaps with logits-cat blocks.
        __shared__ bool is_last;
        __syncthreads();
        if (threadIdx.x == 0) {
            __threadfence();
            unsigned int v = atomicAdd(&g_cnt0, 1u);
            is_last = (v == (GDIM / 16) - 1u);
            if (is_last) g_cnt0 = 0u;
        }
        __syncthreads();
        if (is_last) {
            for (int j = threadIdx.x; j < HDIM; j += blockDim.x) {
                float ig = fast_sigmoid(g_gates0[j]);
                float fg = fast_sigmoid(g_gates0[HDIM + j]);
                float gg = fast_tanh(g_gates0[2 * HDIM + j]);
                float og = fast_sigmoid(g_gates0[3 * HDIM + j]);
                float c_new = fg * cell[j] + ig * gg;
                float h_new = og * fast_tanh(c_new);
                g_h1[j] = h_new;
                out_h1[j] = h_new;
                out_c1[j] = c_new;
            }
        }
    } else if (W < GDIM) {
        int r0 = 2 * (W - GDIM / 2), r1 = r0 + 1;
        const float4* w0 = (const float4*)(w_hh_l1 + (size_t)r0 * 2048);
        const float4* w1 = (const float4*)(w_hh_l1 + (size_t)r1 * 2048);
        const float4* vh = (const float4*)(hidden + HDIM);
        float acc0 = 0.f, acc1 = 0.f;
#pragma unroll
        for (int i = 0; i < 16; i++) {
            float4 x = vh[lane + 32 * i];
            acc0 += f4dot(__ldcs(&w0[lane + 32 * i]), x);
            acc1 += f4dot(__ldcs(&w1[lane + 32 * i]), x);
        }
        acc0 = warp_reduce(acc0);
        acc1 = warp_reduce(acc1);
        if (lane == 0) {
            g_gates1[r0] = acc0 + b_ih_l1[r0] + b_hh_l1[r0];
            g_gates1[r1] = acc1 + b_ih_l1[r1] + b_hh_l1[r1];
        }
    } else {
        int r0 = 2 * (W - GDIM);
        if (r0 < OUTDIM) {
            int r1 = r0 + 1;
            const float4* w0 = (const float4*)(w_out + (size_t)r0 * WOUT_K);
            const float4* w1 = (const float4*)(w_out + (size_t)r1 * WOUT_K);
            const float4* vc = (const float4*)cat;
            float acc0 = 0.f, acc1 = 0.f;
#pragma unroll
            for (int i = 0; i < 8; i++) {
                float4 x = vc[lane + 32 * i];
                acc0 += f4dot(__ldcs(&w0[lane + 32 * i]), x);
                acc1 += f4dot(__ldcs(&w1[lane + 32 * i]), x);
            }
            acc0 = warp_reduce(acc0);
            acc1 = warp_reduce(acc1);
            if (lane == 0) {
                g_logits[r0] = acc0 + b_out[r0];
                g_logits[r1] = acc1 + b_out[r1];
            }
        }
    }
}

// ---------------------------------------------------------------------------
// K2: g_gates1 += w_ih_l1 @ h1, 2 rows/warp.
__global__ void __launch_bounds__(256, 4) k2_l1_ih(const float* __restrict__ w_ih_l1)
{
    int W = (blockIdx.x * blockDim.x + threadIdx.x) >> 5;
    int lane = threadIdx.x & 31;
    int r0 = 2 * W, r1 = r0 + 1;
    const float4* w0 = (const float4*)(w_ih_l1 + (size_t)r0 * 2048);
    const float4* w1 = (const float4*)(w_ih_l1 + (size_t)r1 * 2048);
    const float4* vh = (const float4*)g_h1;
    float acc0 = 0.f, acc1 = 0.f;
#pragma unroll
    for (int i = 0; i < 16; i++) {
        float4 x = vh[lane + 32 * i];
        acc0 += f4dot(__ldcs(&w0[lane + 32 * i]), x);
        acc1 += f4dot(__ldcs(&w1[lane + 32 * i]), x);
    }
    acc0 = warp_reduce(acc0);
    acc1 = warp_reduce(acc1);
    if (lane == 0) {
        g_gates1[r0] += acc0;
        g_gates1[r1] += acc1;
    }
}

// ---------------------------------------------------------------------------
// cell1 (separate tiny kernel)
__global__ void lstm_cell1_kernel(const float* __restrict__ cell,
                                  float* __restrict__ out_h2,
                                  float* __restrict__ out_c2) {
    int j = blockIdx.x * blockDim.x + threadIdx.x;
    if (j >= HDIM) return;
    float ig = fast_sigmoid(g_gates1[j]);
    float fg = fast_sigmoid(g_gates1[HDIM + j]);
    float gg = fast_tanh(g_gates1[2 * HDIM + j]);
    float og = fast_sigmoid(g_gates1[3 * HDIM + j]);
    float c_new = fg * cell[HDIM + j] + ig * gg;
    float h_new = og * fast_tanh(c_new);
    g_h2[j] = h_new;
    out_h2[j] = h_new;
    out_c2[j] = c_new;
}

// ---------------------------------------------------------------------------
// K3: g_logits += w_out[:, 1024:3072] @ h2, 2 rows/warp.
__global__ void __launch_bounds__(256, 4) k3_out_h(const float* __restrict__ w_out)
{
    int W = (blockIdx.x * blockDim.x + threadIdx.x) >> 5;
    int lane = threadIdx.x & 31;
    int r0 = 2 * W;
    if (r0 >= OUTDIM) return;
    int r1 = r0 + 1;
    const float4* w0 = (const float4*)(w_out + (size_t)r0 * WOUT_K + NCAT);
    const float4* w1 = (const float4*)(w_out + (size_t)r1 * WOUT_K + NCAT);
    const float4* vh = (const float4*)g_h2;
    float acc0 = 0.f, acc1 = 0.f;
#pragma unroll
    for (int i = 0; i < 16; i++) {
        float4 x = vh[lane + 32 * i];
        acc0 += f4dot(__ldcs(&w0[lane + 32 * i]), x);
        acc1 += f4dot(__ldcs(&w1[lane + 32 * i]), x);
    }
    acc0 = warp_reduce(acc0);
    acc1 = warp_reduce(acc1);
    if (lane == 0) {
        g_logits[r0] += acc0;
        g_logits[r1] += acc1;
    }
}

// ---------------------------------------------------------------------------
// Parallel log_softmax, stage 1: per-chunk (max, sum-exp) partials.
__global__ void softmax_partials(void) {
    __shared__ float red[8];
    int c = blockIdx.x;           // chunk id, 64 chunks of 500
    int tid = threadIdx.x;        // 256 threads
    int lane = tid & 31, wid = tid >> 5;
    int base = c * SMX_CHUNK;

    float m = -INFINITY;
    for (int i = tid; i < SMX_CHUNK; i += 256) m = fmaxf(m, g_logits[base + i]);
#pragma unroll
    for (int off = 16; off; off >>= 1)
        m = fmaxf(m, __shfl_xor_sync(0xffffffffu, m, off));
    if (lane == 0) red[wid] = m;
    __syncthreads();
    if (wid == 0) {
        float v = (lane < 8) ? red[lane] : -INFINITY;
#pragma unroll
        for (int off = 4; off; off >>= 1)
            v = fmaxf(v, __shfl_xor_sync(0xffffffffu, v, off));
        if (lane == 0) red[0] = v;
    }
    __syncthreads();
    m = red[0];
    __syncthreads();

    float s = 0.f;
    for (int i = tid; i < SMX_CHUNK; i += 256) s += __expf(g_logits[base + i] - m);
#pragma unroll
    for (int off = 16; off; off >>= 1)
        s += __shfl_xor_sync(0xffffffffu, s, off);
    if (lane == 0) red[wid] = s;
    __syncthreads();
    if (wid == 0) {
        float v = (lane < 8) ? red[lane] : 0.f;
#pragma unroll
        for (int off = 4; off; off >>= 1)
            v += __shfl_xor_sync(0xffffffffu, v, off);
        if (lane == 0) { g_pmax[c] = m; g_psum[c] = v; }
    }
}

// Stage 2: each block recombines the 64 partials into lse, writes its chunk.
__global__ void softmax_finalize(float* __restrict__ out) {
    __shared__ float s_lse;
    int tid = threadIdx.x;  // 256
    if (tid < 32) {
        float m = (tid < SMX_CHUNKS) ? g_pmax[tid] : -INFINITY;
        float mm = (tid + 32 < SMX_CHUNKS) ? g_pmax[tid + 32] : -INFINITY;
        m = fmaxf(m, mm);
#pragma unroll
        for (int off = 16; off; off >>= 1)
            m = fmaxf(m, __shfl_xor_sync(0xffffffffu, m, off));
        float s = 0.f;
        if (tid < SMX_CHUNKS) s += g_psum[tid] * __expf(g_pmax[tid] - m);
        if (tid + 32 < SMX_CHUNKS) s += g_psum[tid + 32] * __expf(g_pmax[tid + 32] - m);
#pragma unroll
        for (int off = 16; off; off >>= 1)
            s += __shfl_xor_sync(0xffffffffu, s, off);
        if (tid == 0) s_lse = m + __logf(s);
    }
    __syncthreads();
    float lse = s_lse;
    int i = blockIdx.x * 256 + tid;
    if (i < OUTDIM) out[i] = g_logits[i] - lse;
}

// ---------------------------------------------------------------------------
extern "C" void kernel_launch(void* const* d_in, const int* in_sizes, int n_in,
                              void* d_out, int out_size) {
    const float* category = (const float*)d_in[0];
    const float* input    = (const float*)d_in[1];
    const float* hidden   = (const float*)d_in[2];
    const float* cell     = (const float*)d_in[3];
    const float* w_ih_l0  = (const float*)d_in[4];
    const float* w_hh_l0  = (const float*)d_in[5];
    const float* b_ih_l0  = (const float*)d_in[6];
    const float* b_hh_l0  = (const float*)d_in[7];
    const float* w_ih_l1  = (const float*)d_in[8];
    const float* w_hh_l1  = (const float*)d_in[9];
    const float* b_ih_l1  = (const float*)d_in[10];
    const float* b_hh_l1  = (const float*)d_in[11];
    const float* w_out    = (const float*)d_in[12];
    const float* b_out    = (const float*)d_in[13];

    float* out = (float*)d_out;
    float* out_logp = out;
    float* out_h1 = out + OUTDIM;
    float* out_h2 = out + OUTDIM + HDIM;
    float* out_c1 = out + OUTDIM + 2 * HDIM;
    float* out_c2 = out + OUTDIM + 3 * HDIM;

    // K1: 3024 blocks = 512 gates0 + 512 gates1-partial + 2000 logits-cat
    k1_input_matvecs<<<3024, 256>>>(
        category, input, hidden, cell,
        w_ih_l0, w_hh_l0, b_ih_l0, b_hh_l0,
        w_hh_l1, b_ih_l1, b_hh_l1,
        w_out, b_out, out_h1, out_c1);

    // K2: 8192 rows, 2 rows/warp, 8 warps/block -> 512 blocks
    k2_l1_ih<<<GDIM / 16, 256>>>(w_ih_l1);

    // cell1
    lstm_cell1_kernel<<<HDIM / 256, 256>>>(cell, out_h2, out_c2);

    // K3: 32000 rows, 2 rows/warp -> 2000 blocks
    k3_out_h<<<OUTDIM / 16, 256>>>(w_out);

    // parallel log_softmax: partials then finalize
    softmax_partials<<<SMX_CHUNKS, 256>>>();
    softmax_finalize<<<(OUTDIM + 255) / 256, 256>>>(out_logp);
}